// round 15
// baseline (speedup 1.0000x reference)
#include <cuda_runtime.h>
#include <cuda_bf16.h>
#include <math.h>
#include <stdint.h>

#define NPIX 262144   // 512*512
#define NIMG 24       // 8 batch * 3 channels

// ---------------- scratch (device globals) -----------------------------------
static __device__ float2 g_nfq[NIMG * NPIX];     // packed spectrum Z = FFT(noisy + i*clean)
static __device__ float2 g_cfq[NIMG * NPIX];     // inverse-pass intermediate (12 pair images)
static __device__ float  g_fin[8 * 6 * NPIX];    // log-mag channels (B,6,512,512)
static __device__ float  g_p1 [8 * 16 * 65536];  // pooled conv1 out (256^2)
static __device__ float  g_p2 [8 * 32 * 16384];  // pooled conv2 out (128^2)
static __device__ float  g_part[512 * 32];       // conv3 per-block partial sums
static __device__ float  g_h  [8 * 256];
static __device__ float  g_vset[8 * 100];
static __device__ float2 g_tw [512];             // W_512^k

// ---------------- twiddles ---------------------------------------------------
__global__ void init_tw_kernel() {
    int k = threadIdx.x;
    if (k < 512) {
        double s, c;
        sincospi(-(double)k / 256.0, &s, &c);
        g_tw[k] = make_float2((float)c, (float)s);
    }
}

// ---------------- complex helpers --------------------------------------------
__device__ __forceinline__ float2 cadd(float2 a, float2 b){ return make_float2(a.x+b.x, a.y+b.y); }
__device__ __forceinline__ float2 csub(float2 a, float2 b){ return make_float2(a.x-b.x, a.y-b.y); }
template<int INV>
__device__ __forceinline__ float2 ctw(float2 a, float2 w) {
    if (!INV) return make_float2(a.x*w.x - a.y*w.y, a.x*w.y + a.y*w.x);
    else      return make_float2(a.x*w.x + a.y*w.y, a.y*w.x - a.x*w.y);
}

// ---------------- 8-point DFT ------------------------------------------------
template<int INV>
__device__ __forceinline__ void dft8(float2* a) {
    const float C = 0.70710678118654752f;
    float2 b0 = cadd(a[0], a[4]), t4 = csub(a[0], a[4]);
    float2 b1 = cadd(a[1], a[5]), t5 = csub(a[1], a[5]);
    float2 b2 = cadd(a[2], a[6]), t6 = csub(a[2], a[6]);
    float2 b3 = cadd(a[3], a[7]), t7 = csub(a[3], a[7]);
    float2 b5, b6, b7;
    if (!INV) {
        b5 = make_float2(C*(t5.x + t5.y), C*(t5.y - t5.x));
        b6 = make_float2(t6.y, -t6.x);
        b7 = make_float2(C*(t7.y - t7.x), -C*(t7.x + t7.y));
    } else {
        b5 = make_float2(C*(t5.x - t5.y), C*(t5.y + t5.x));
        b6 = make_float2(-t6.y, t6.x);
        b7 = make_float2(-C*(t7.x + t7.y), C*(t7.x - t7.y));
    }
    float2 c0 = cadd(b0, b2), c2 = csub(b0, b2);
    float2 c1 = cadd(b1, b3), t3 = csub(b1, b3);
    float2 c4 = cadd(t4, b6), c6 = csub(t4, b6);
    float2 c5 = cadd(b5, b7), t7b = csub(b5, b7);
    float2 c3 = (!INV) ? make_float2(t3.y, -t3.x)  : make_float2(-t3.y, t3.x);
    float2 c7 = (!INV) ? make_float2(t7b.y, -t7b.x): make_float2(-t7b.y, t7b.x);
    a[0] = cadd(c0, c1); a[4] = csub(c0, c1);
    a[2] = cadd(c2, c3); a[6] = csub(c2, c3);
    a[1] = cadd(c4, c5); a[5] = csub(c4, c5);
    a[3] = cadd(c6, c7); a[7] = csub(c6, c7);
}

#define FPAD(p) ((p) + ((p) >> 3))
__device__ __forceinline__ int drev(int i) {
    return ((i & 7) << 6) | (i & 56) | (i >> 6);
}

template<int INV>
__device__ __forceinline__ void fft512_stages(float2 (*sd)[576], const float2* stw) {
    int tid = threadIdx.x;
    float2* s = sd[tid >> 6];
    int t = tid & 63;
    {
        float2 a[8];
#pragma unroll
        for (int j = 0; j < 8; j++) { int p = 8*t + j; a[j] = s[FPAD(p)]; }
        dft8<INV>(a);
#pragma unroll
        for (int m = 0; m < 8; m++) { int p = 8*t + m; s[FPAD(p)] = a[m]; }
    }
    __syncthreads();
    {
        int k = t & 7, base = ((t >> 3) << 6) + k;
        float2 a[8];
        a[0] = s[FPAD(base)];
#pragma unroll
        for (int j = 1; j < 8; j++) {
            int p = base + 8*j;
            a[j] = ctw<INV>(s[FPAD(p)], stw[8*j*k]);
        }
        dft8<INV>(a);
#pragma unroll
        for (int m = 0; m < 8; m++) { int p = base + 8*m; s[FPAD(p)] = a[m]; }
    }
    __syncthreads();
    {
        float2 a[8];
        a[0] = s[FPAD(t)];
#pragma unroll
        for (int j = 1; j < 8; j++) {
            int p = t + 64*j;
            a[j] = ctw<INV>(s[FPAD(p)], stw[j*t]);
        }
        dft8<INV>(a);
#pragma unroll
        for (int m = 0; m < 8; m++) { int p = t + 64*m; s[FPAD(p)] = a[m]; }
    }
    __syncthreads();
}

// ---------------- forward FFT rows: z = noisy + i*clean ----------------------
__global__ void __launch_bounds__(512)
fwd_rows_kernel(const float* __restrict__ noisy, const float* __restrict__ clean) {
    __shared__ float2 sd[8][576];
    __shared__ float2 stw[512];
    int tid = threadIdx.x;
    stw[tid] = g_tw[tid];
    int img = blockIdx.y;            // 0..23
    int r0  = blockIdx.x * 8;
    size_t base = (size_t)img * NPIX;
#pragma unroll
    for (int row = 0; row < 8; row++) {
        size_t gi = base + (size_t)(r0 + row) * 512 + tid;
        sd[row][FPAD(drev(tid))] = make_float2(noisy[gi], clean[gi]);
    }
    __syncthreads();
    fft512_stages<0>(sd, stw);
#pragma unroll
    for (int row = 0; row < 8; row++)
        g_nfq[base + (size_t)(r0 + row) * 512 + tid] = sd[row][FPAD(tid)];
}

// ---------------- forward FFT cols -------------------------------------------
__global__ void __launch_bounds__(512)
fwd_cols_kernel() {
    __shared__ float2 sd[8][576];
    __shared__ float2 stw[512];
    int tid = threadIdx.x;
    stw[tid] = g_tw[tid];
    int img = blockIdx.y;            // 0..23
    int c0  = blockIdx.x * 8;
    float2* buf = g_nfq + (size_t)img * NPIX;
    int c = tid & 7;
#pragma unroll
    for (int it = 0; it < 8; it++) {
        int r = it * 64 + (tid >> 3);
        sd[c][FPAD(drev(r))] = buf[(size_t)r * 512 + c0 + c];
    }
    __syncthreads();
    fft512_stages<0>(sd, stw);
#pragma unroll
    for (int it = 0; it < 8; it++) {
        int r = it * 64 + (tid >> 3);
        buf[(size_t)r * 512 + c0 + c] = sd[c][FPAD(r)];
    }
}

// ---------------- unpack Hermitian pair -> log-mag channels (f32) ------------
__global__ void unpack_logmag_kernel() {
    const int NC = 257;
    int idx = blockIdx.x * blockDim.x + threadIdx.x;
    if (idx >= NIMG * 512 * NC) return;
    int img = idx / (512 * NC);
    int rem = idx - img * (512 * NC);
    int r = rem / NC;
    int c = rem - r * NC;
    int mr = (512 - r) & 511, mc = (512 - c) & 511;
    float2 Zk = g_nfq[(size_t)img * NPIX + ((size_t)r << 9) + c];
    float2 Zm = g_nfq[(size_t)img * NPIX + ((size_t)mr << 9) + mc];
    float Nx = 0.5f * (Zk.x + Zm.x), Ny = 0.5f * (Zk.y - Zm.y);
    float Dx = 0.5f * (Zk.x - Zm.x), Dy = 0.5f * (Zk.y + Zm.y);
    float vN = log10f(sqrtf(Nx * Nx + Ny * Ny) + 1.f);
    float vC = log10f(sqrtf(Dx * Dx + Dy * Dy) + 1.f);
    int b = img / 3, ch = img - 3 * b;
    size_t o1 = ((size_t)((r + 256) & 511) << 9) + ((c + 256) & 511);
    size_t o2 = ((size_t)((mr + 256) & 511) << 9) + ((mc + 256) & 511);
    float* finN = g_fin + (size_t)(b * 6 + ch) * NPIX;
    float* finC = g_fin + (size_t)(b * 6 + 3 + ch) * NPIX;
    finN[o1] = vN; finN[o2] = vN;
    finC[o1] = vC; finC[o2] = vC;
}

// ---------------- bf16 MMA + ldmatrix ----------------------------------------
#define MMA_BF16(d, a0,a1,a2,a3, b0,b1)                                        \
    asm("mma.sync.aligned.m16n8k16.row.col.f32.bf16.bf16.f32 "                 \
        "{%0,%1,%2,%3}, {%4,%5,%6,%7}, {%8,%9}, {%0,%1,%2,%3};"                \
        : "+f"(d[0]), "+f"(d[1]), "+f"(d[2]), "+f"(d[3])                       \
        : "r"(a0), "r"(a1), "r"(a2), "r"(a3), "r"(b0), "r"(b1))

#define LDSM_X4(r0,r1,r2,r3, addr)                                             \
    asm volatile("ldmatrix.sync.aligned.m8n8.x4.shared.b16 {%0,%1,%2,%3}, [%4];" \
        : "=r"(r0), "=r"(r1), "=r"(r2), "=r"(r3) : "r"(addr))

// ---------------- implicit-GEMM 3x3 conv, bf16 m16n8k16, ldmatrix A ----------
// K-order: chunk = (tap, 16 contiguous channels). A tile rows = 16 x-pixels,
// row bytes contiguous in smem (channel-fastest) -> ldmatrix.x4 per m-tile.
// CS: padded channel stride (conflict-free ldmatrix phases, 16B-aligned rows).
template<int CIN, int CS, int NCHUNK, int COUT, int H, int W, bool GATHER, bool MEAN>
__global__ void __launch_bounds__(256)
convmma_kernel(const float* __restrict__ in,
               const float* __restrict__ noisy, const float* __restrict__ clean,
               const float* __restrict__ fin,
               const float* __restrict__ wgt,
               const float* __restrict__ bias, float* __restrict__ out) {
    constexpr int OGC = COUT / 16;
    constexpr int SIN_BYTES = 648 * CS * 2;   // 18*36 pixels * CS bf16

    extern __shared__ char smemc[];
    __nv_bfloat16* sIn = (__nv_bfloat16*)smemc;
    unsigned* wPk = (unsigned*)(smemc + SIN_BYTES);

    int tid = threadIdx.x;
    int bz = blockIdx.z;
    int og = bz % OGC;
    int b  = bz / OGC;
    int x0 = blockIdx.x * 32, y0 = blockIdx.y * 16;

    // ---- zero sIn (pad channels must be 0: garbage*0 could be NaN)
    {
        uint4 z4 = make_uint4(0, 0, 0, 0);
        uint4* zp = (uint4*)sIn;
        for (int i = tid; i < SIN_BYTES / 16; i += 256) zp[i] = z4;
    }
    // ---- weights packed as bf16x2 fragments; chunk-order k = channel
    for (int e = tid; e < NCHUNK * 8 * 16; e += 256) {
        int idx = e >> 4;            // chunk*8 + pair
        int o   = e & 15;
        int c   = idx >> 3, p = idx & 7;
        int tap = (CIN == 32) ? (c >> 1) : c;
        int cb  = (CIN == 32) ? ((c & 1) * 16) : 0;
        int ch0 = cb + 2 * p, ch1 = ch0 + 1;
        float w0 = (ch0 < CIN) ? wgt[((og * 16 + o) * CIN + ch0) * 9 + tap] : 0.f;
        float w1 = (ch1 < CIN) ? wgt[((og * 16 + o) * CIN + ch1) * 9 + tap] : 0.f;
        __nv_bfloat162 pr = __floats2bfloat162_rn(w0, w1);
        wPk[idx * 20 + o] = *(unsigned*)&pr;
    }
    __syncthreads();
    // ---- input tile (halo): fused single loop (high MLP)
    for (int e = tid; e < 18 * 36 * CIN; e += 256) {
        int ic = e / 648;
        int rr = e - ic * 648;
        int r = rr / 36, cc = rr - r * 36;
        int gy = y0 + r - 1, gx = x0 + cc - 1;
        float v = 0.f;
        if (cc < 34 && (unsigned)gy < (unsigned)H && (unsigned)gx < (unsigned)W) {
            if (GATHER) {
                int grp = ic / 3, sub = ic - 3 * grp;
                const float* src =
                    (grp == 0) ? noisy + (size_t)(b * 3 + sub) * NPIX :
                    (grp == 1) ? fin   + (size_t)(b * 6 + sub) * NPIX :
                    (grp == 2) ? clean + (size_t)(b * 3 + sub) * NPIX :
                                 fin   + (size_t)(b * 6 + 3 + sub) * NPIX;
                v = src[((size_t)gy << 9) + gx];
            } else {
                v = in[((size_t)(b * CIN + ic) * H + gy) * W + gx];
            }
        }
        sIn[rr * CS + ic] = __float2bfloat16_rn(v);
    }
    __syncthreads();

    int lane = tid & 31, w = tid >> 5;
    int gid = lane >> 2, tig = lane & 3;

    float acc[4][2][4];
#pragma unroll
    for (int mt = 0; mt < 4; mt++)
#pragma unroll
        for (int nt = 0; nt < 2; nt++)
#pragma unroll
            for (int c = 0; c < 4; c++) acc[mt][nt][c] = 0.f;

    // ---- ldmatrix base addresses: lanes 0-15 -> tile rows 0-15 (k bytes 0-15),
    //      lanes 16-31 -> same rows, +16B (k bytes 16-31)
    unsigned sbase = (unsigned)__cvta_generic_to_shared(sIn);
    int ro = lane & 15, hi = lane >> 4;
    unsigned lmb[4];
#pragma unroll
    for (int mt = 0; mt < 4; mt++) {
        int pix = (2 * w + (mt & 1)) * 36 + (mt >> 1) * 16 + ro;
        lmb[mt] = sbase + (unsigned)(pix * CS * 2 + hi * 16);
    }

#pragma unroll
    for (int c = 0; c < NCHUNK; c++) {
        const int tap = (CIN == 32) ? (c >> 1) : c;
        const int cb  = (CIN == 32) ? ((c & 1) * 16) : 0;
        const int toff = (((tap / 3) * 36 + (tap % 3)) * CS + cb) * 2;
        unsigned b0[2], b1[2];
#pragma unroll
        for (int nt = 0; nt < 2; nt++) {
            b0[nt] = wPk[(c * 8 + tig) * 20 + nt * 8 + gid];
            b1[nt] = wPk[(c * 8 + tig + 4) * 20 + nt * 8 + gid];
        }
#pragma unroll
        for (int mt = 0; mt < 4; mt++) {
            unsigned a0, a1, a2, a3;
            LDSM_X4(a0, a1, a2, a3, lmb[mt] + toff);
#pragma unroll
            for (int nt = 0; nt < 2; nt++)
                MMA_BF16(acc[mt][nt], a0, a1, a2, a3, b0[nt], b1[nt]);
        }
    }

    if (MEAN) {
        __shared__ float sred[8][16];
        int sblk = blockIdx.y * gridDim.x + blockIdx.x;   // 0..31
#pragma unroll
        for (int nt = 0; nt < 2; nt++)
#pragma unroll
            for (int j = 0; j < 2; j++) {
                int o = og * 16 + nt * 8 + 2 * tig + j;
                float bv = bias[o];
                float s = 0.f;
#pragma unroll
                for (int mt = 0; mt < 4; mt++)
                    s += fmaxf(acc[mt][nt][j] + bv, 0.f) +
                         fmaxf(acc[mt][nt][j + 2] + bv, 0.f);
                s += __shfl_xor_sync(0xffffffffu, s, 4);
                s += __shfl_xor_sync(0xffffffffu, s, 8);
                s += __shfl_xor_sync(0xffffffffu, s, 16);
                if (gid == 0) sred[w][nt * 8 + 2 * tig + j] = s;
            }
        __syncthreads();
        if (tid < 16) {
            float s = 0.f;
#pragma unroll
            for (int ww = 0; ww < 8; ww++) s += sred[ww][tid];
            out[(size_t)(b * COUT + og * 16 + tid) * 32 + sblk] = s;
        }
    } else {
        const int Ho = H / 2, Wo = W / 2;
        int oy = (y0 >> 1) + w;
#pragma unroll
        for (int half = 0; half < 2; half++) {
#pragma unroll
            for (int nt = 0; nt < 2; nt++)
#pragma unroll
                for (int c = 0; c < 2; c++) {
                    int o = og * 16 + nt * 8 + 2 * tig + c;
                    float bv = bias[o];
                    float sa = fmaxf(acc[half*2][nt][c]   + bv, 0.f) +
                               fmaxf(acc[half*2+1][nt][c] + bv, 0.f);
                    float sb = fmaxf(acc[half*2][nt][c+2]   + bv, 0.f) +
                               fmaxf(acc[half*2+1][nt][c+2] + bv, 0.f);
                    sa += __shfl_xor_sync(0xffffffffu, sa, 4);
                    sb += __shfl_xor_sync(0xffffffffu, sb, 4);
                    if (!(gid & 1)) {
                        int oxa = (x0 + half * 16 + gid) >> 1;
                        size_t base = ((size_t)(b * COUT + o) * Ho + oy) * Wo;
                        out[base + oxa]     = 0.25f * sa;
                        out[base + oxa + 4] = 0.25f * sb;
                    }
                }
        }
    }
}

// ---------------- fc1 (fused final mean reduction) ---------------------------
__global__ void __launch_bounds__(256)
fc1_kernel(const float* __restrict__ w, const float* __restrict__ bias,
           const float* __restrict__ part) {
    __shared__ float sf[64];
    int b = blockIdx.x, t = threadIdx.x;
    if (t < 64) {
        float s = 0.f;
        const float* p = part + (size_t)(b * 64 + t) * 32;
#pragma unroll
        for (int i = 0; i < 32; i++) s += p[i];
        sf[t] = s * (1.f / 16384.f);
    }
    __syncthreads();
    float s = 0.f;
    const float* wr = w + (size_t)t * 64;
#pragma unroll
    for (int i = 0; i < 64; i++) s = fmaf(wr[i], sf[i], s);
    g_h[b * 256 + t] = s + bias[t];
}

// ---------------- head -------------------------------------------------------
__global__ void __launch_bounds__(128)
head_kernel(const float* __restrict__ w, const float* __restrict__ bias) {
    __shared__ float sh[256];
    __shared__ float red[128];
    int j = blockIdx.x;
    int b = blockIdx.y;
    int t = threadIdx.x;
    for (int i = t; i < 256; i += 128) sh[i] = g_h[b * 256 + i];
    __syncthreads();
    float z = -3.4e38f;
    if (t < 100) {
        const float* wr = w + (size_t)(j * 100 + t) * 256;
        float s = 0.f;
        for (int i = 0; i < 256; i++) s = fmaf(wr[i], sh[i], s);
        z = (s + bias[j * 100 + t]) * 0.1f;
    }
    red[t] = z;
    __syncthreads();
    for (int off = 64; off; off >>= 1) {
        if (t < off) red[t] = fmaxf(red[t], red[t + off]);
        __syncthreads();
    }
    float m = red[0];
    __syncthreads();
    float p = (t < 100) ? expf(z - m) : 0.f;
    red[t] = p;
    __syncthreads();
    for (int off = 64; off; off >>= 1) {
        if (t < off) red[t] += red[t + off];
        __syncthreads();
    }
    float S = red[0];
    __syncthreads();
    float rf = ((float)t + 1.0f) * 0.01f;
    red[t] = p * rf;
    __syncthreads();
    for (int off = 64; off; off >>= 1) {
        if (t < off) red[t] += red[t + off];
        __syncthreads();
    }
    if (t == 0) g_vset[b * 100 + j] = red[0] / S;
}

// ---------------- radial mask ------------------------------------------------
__global__ void mask_kernel(float* __restrict__ outMask) {
    int idx = blockIdx.x * blockDim.x + threadIdx.x;
    if (idx >= 8 * NPIX) return;
    int b = idx >> 18;
    int pix = idx & (NPIX - 1);
    int y = pix >> 9, x = pix & 511;
    float dy = (float)y - 256.f, dx = (float)x - 256.f;
    float dist = sqrtf(dy * dy + dx * dx);
    const float MAXR = 362.03867196751236f;
    int lo = 0, hi = 100;
    while (lo < hi) {
        int mid = (lo + hi) >> 1;
        float r = MAXR * (((float)(mid + 1)) * 0.01f);
        if (r <= dist) lo = mid + 1; else hi = mid;
    }
    outMask[idx] = (lo < 100) ? g_vset[b * 100 + lo] : 0.f;
}

// ---------------- inverse FFT rows: build D_a + i*D_b on the fly -------------
__global__ void __launch_bounds__(512)
inv_rows_kernel(const float* __restrict__ maskp) {
    __shared__ float2 sd[8][576];
    __shared__ float2 stw[512];
    int tid = threadIdx.x;
    stw[tid] = g_tw[tid];
    int p   = blockIdx.y;     // 0..11
    int r0  = blockIdx.x * 8;
    int ia = 2 * p, ib = 2 * p + 1;
    int ba = ia / 3, bb = ib / 3;
    int c  = tid;
    int mc = (512 - c) & 511;
    int xs = (c + 256) & 511;
#pragma unroll
    for (int row = 0; row < 8; row++) {
        int gr = r0 + row;
        int mr = (512 - gr) & 511;
        int ys = (gr + 256) & 511;
        size_t ofk = ((size_t)gr << 9) + c;
        size_t ofm = ((size_t)mr << 9) + mc;
        float2 Zk = g_nfq[(size_t)ia * NPIX + ofk];
        float2 Zm = g_nfq[(size_t)ia * NPIX + ofm];
        float Nx = 0.5f*(Zk.x + Zm.x), Ny = 0.5f*(Zk.y - Zm.y);
        float Dx = 0.5f*(Zk.x - Zm.x), Dy = 0.5f*(Zk.y + Zm.y);
        float ma = maskp[(size_t)ba * NPIX + ((size_t)ys << 9) + xs];
        float Dax = ma * (Nx - Dy);
        float Day = ma * (Ny + Dx);
        Zk = g_nfq[(size_t)ib * NPIX + ofk];
        Zm = g_nfq[(size_t)ib * NPIX + ofm];
        Nx = 0.5f*(Zk.x + Zm.x); Ny = 0.5f*(Zk.y - Zm.y);
        Dx = 0.5f*(Zk.x - Zm.x); Dy = 0.5f*(Zk.y + Zm.y);
        float mb = maskp[(size_t)bb * NPIX + ((size_t)ys << 9) + xs];
        float Dbx = mb * (Nx - Dy);
        float Dby = mb * (Ny + Dx);
        sd[row][FPAD(drev(tid))] = make_float2(Dax - Dby, Day + Dbx);
    }
    __syncthreads();
    fft512_stages<1>(sd, stw);
#pragma unroll
    for (int row = 0; row < 8; row++)
        g_cfq[(size_t)p * NPIX + (size_t)(r0 + row) * 512 + tid] = sd[row][FPAD(tid)];
}

// ---------------- inverse FFT cols + hard/easy for both pair images ----------
__global__ void __launch_bounds__(512)
inv_cols_kernel(const float* __restrict__ clean, const float* __restrict__ noisy,
                float* __restrict__ hard, float* __restrict__ easy) {
    __shared__ float2 sd[8][576];
    __shared__ float2 stw[512];
    int tid = threadIdx.x;
    stw[tid] = g_tw[tid];
    int p   = blockIdx.y;     // 0..11
    int c0  = blockIdx.x * 8;
    float2* buf = g_cfq + (size_t)p * NPIX;
    int c = tid & 7;
#pragma unroll
    for (int it = 0; it < 8; it++) {
        int r = it * 64 + (tid >> 3);
        sd[c][FPAD(drev(r))] = buf[(size_t)r * 512 + c0 + c];
    }
    __syncthreads();
    fft512_stages<1>(sd, stw);
    const float scale = 1.f / 262144.f;
    int ia = 2 * p, ib = 2 * p + 1;
#pragma unroll
    for (int it = 0; it < 8; it++) {
        int r = it * 64 + (tid >> 3);
        float2 v = sd[c][FPAD(r)];
        float da = v.x * scale;
        float db = v.y * scale;
        size_t gia = (size_t)ia * NPIX + (size_t)r * 512 + c0 + c;
        size_t gib = (size_t)ib * NPIX + (size_t)r * 512 + c0 + c;
        hard[gia] = clean[gia] + da;
        easy[gia] = noisy[gia] - da;
        hard[gib] = clean[gib] + db;
        easy[gib] = noisy[gib] - db;
    }
}

// ---------------- launch ------------------------------------------------------
extern "C" void kernel_launch(void* const* d_in, const int* in_sizes, int n_in,
                              void* d_out, int out_size) {
    const float* clean = (const float*)d_in[0];
    const float* noisy = (const float*)d_in[1];
    const float* c1w = (const float*)d_in[2];
    const float* c1b = (const float*)d_in[3];
    const float* c2w = (const float*)d_in[4];
    const float* c2b = (const float*)d_in[5];
    const float* c3w = (const float*)d_in[6];
    const float* c3b = (const float*)d_in[7];
    const float* f1w = (const float*)d_in[8];
    const float* f1b = (const float*)d_in[9];
    const float* f2w = (const float*)d_in[10];
    const float* f2b = (const float*)d_in[11];

    float* hard  = (float*)d_out;
    float* easy  = hard + 6291456;
    float* maskp = easy + 6291456;

    float *p_fin, *p_p1, *p_p2, *p_part;
    cudaGetSymbolAddress((void**)&p_fin, g_fin);
    cudaGetSymbolAddress((void**)&p_p1, g_p1);
    cudaGetSymbolAddress((void**)&p_p2, g_p2);
    cudaGetSymbolAddress((void**)&p_part, g_part);

    // smem bytes: sIn(648*CS*2) + wPk(NCHUNK*8*20*4)
    const int smem1 = 648 * 24 * 2 + 9 * 160 * 4;    // 36864
    const int smem2 = 648 * 24 * 2 + 9 * 160 * 4;    // 36864
    const int smem3 = 648 * 40 * 2 + 18 * 160 * 4;   // 63360
    cudaFuncSetAttribute(convmma_kernel<12, 24, 9, 16, 512, 512, true, false>,
                         cudaFuncAttributeMaxDynamicSharedMemorySize, smem1);
    cudaFuncSetAttribute(convmma_kernel<16, 24, 9, 32, 256, 256, false, false>,
                         cudaFuncAttributeMaxDynamicSharedMemorySize, smem2);
    cudaFuncSetAttribute(convmma_kernel<32, 40, 18, 64, 128, 128, false, true>,
                         cudaFuncAttributeMaxDynamicSharedMemorySize, smem3);

    init_tw_kernel<<<1, 512>>>();

    fwd_rows_kernel<<<dim3(64, 24), 512>>>(noisy, clean);
    fwd_cols_kernel<<<dim3(64, 24), 512>>>();
    unpack_logmag_kernel<<<(NIMG * 512 * 257 + 255) / 256, 256>>>();

    convmma_kernel<12, 24, 9, 16, 512, 512, true, false><<<dim3(16, 32, 8), 256, smem1>>>(
        nullptr, noisy, clean, p_fin, c1w, c1b, p_p1);
    convmma_kernel<16, 24, 9, 32, 256, 256, false, false><<<dim3(8, 16, 16), 256, smem2>>>(
        p_p1, nullptr, nullptr, nullptr, c2w, c2b, p_p2);
    convmma_kernel<32, 40, 18, 64, 128, 128, false, true><<<dim3(4, 8, 32), 256, smem3>>>(
        p_p2, nullptr, nullptr, nullptr, c3w, c3b, p_part);

    fc1_kernel<<<8, 256>>>(f1w, f1b, p_part);
    head_kernel<<<dim3(100, 8), 128>>>(f2w, f2b);

    mask_kernel<<<(8 * NPIX + 255) / 256, 256>>>(maskp);
    inv_rows_kernel<<<dim3(64, 12), 512>>>(maskp);
    inv_cols_kernel<<<dim3(64, 12), 512>>>(clean, noisy, hard, easy);
}

// round 16
// speedup vs baseline: 1.2285x; 1.2285x over previous
#include <cuda_runtime.h>
#include <cuda_bf16.h>
#include <math.h>
#include <stdint.h>

#define NPIX 262144   // 512*512
#define NIMG 24       // 8 batch * 3 channels

// ---------------- scratch (device globals) -----------------------------------
static __device__ float2 g_nfq[NIMG * NPIX];     // packed spectrum Z = FFT(noisy + i*clean)
static __device__ float2 g_cfq[NIMG * NPIX];     // inverse-pass intermediate (12 pair images)
static __device__ float  g_fin[8 * 6 * NPIX];    // log-mag channels (B,6,512,512)
static __device__ float  g_p1 [8 * 16 * 65536];  // pooled conv1 out (256^2)
static __device__ float  g_p2 [8 * 32 * 16384];  // pooled conv2 out (128^2)
static __device__ float  g_part[512 * 32];       // conv3 per-block partial sums
static __device__ float  g_h  [8 * 256];
static __device__ float  g_vset[8 * 100];
static __device__ float2 g_tw [512];             // W_512^k

// ---------------- twiddles ---------------------------------------------------
__global__ void init_tw_kernel() {
    int k = threadIdx.x;
    if (k < 512) {
        double s, c;
        sincospi(-(double)k / 256.0, &s, &c);
        g_tw[k] = make_float2((float)c, (float)s);
    }
}

// ---------------- complex helpers --------------------------------------------
__device__ __forceinline__ float2 cadd(float2 a, float2 b){ return make_float2(a.x+b.x, a.y+b.y); }
__device__ __forceinline__ float2 csub(float2 a, float2 b){ return make_float2(a.x-b.x, a.y-b.y); }
template<int INV>
__device__ __forceinline__ float2 ctw(float2 a, float2 w) {
    if (!INV) return make_float2(a.x*w.x - a.y*w.y, a.x*w.y + a.y*w.x);
    else      return make_float2(a.x*w.x + a.y*w.y, a.y*w.x - a.x*w.y);
}

// ---------------- 8-point DFT ------------------------------------------------
template<int INV>
__device__ __forceinline__ void dft8(float2* a) {
    const float C = 0.70710678118654752f;
    float2 b0 = cadd(a[0], a[4]), t4 = csub(a[0], a[4]);
    float2 b1 = cadd(a[1], a[5]), t5 = csub(a[1], a[5]);
    float2 b2 = cadd(a[2], a[6]), t6 = csub(a[2], a[6]);
    float2 b3 = cadd(a[3], a[7]), t7 = csub(a[3], a[7]);
    float2 b5, b6, b7;
    if (!INV) {
        b5 = make_float2(C*(t5.x + t5.y), C*(t5.y - t5.x));
        b6 = make_float2(t6.y, -t6.x);
        b7 = make_float2(C*(t7.y - t7.x), -C*(t7.x + t7.y));
    } else {
        b5 = make_float2(C*(t5.x - t5.y), C*(t5.y + t5.x));
        b6 = make_float2(-t6.y, t6.x);
        b7 = make_float2(-C*(t7.x + t7.y), C*(t7.x - t7.y));
    }
    float2 c0 = cadd(b0, b2), c2 = csub(b0, b2);
    float2 c1 = cadd(b1, b3), t3 = csub(b1, b3);
    float2 c4 = cadd(t4, b6), c6 = csub(t4, b6);
    float2 c5 = cadd(b5, b7), t7b = csub(b5, b7);
    float2 c3 = (!INV) ? make_float2(t3.y, -t3.x)  : make_float2(-t3.y, t3.x);
    float2 c7 = (!INV) ? make_float2(t7b.y, -t7b.x): make_float2(-t7b.y, t7b.x);
    a[0] = cadd(c0, c1); a[4] = csub(c0, c1);
    a[2] = cadd(c2, c3); a[6] = csub(c2, c3);
    a[1] = cadd(c4, c5); a[5] = csub(c4, c5);
    a[3] = cadd(c6, c7); a[7] = csub(c6, c7);
}

#define FPAD(p) ((p) + ((p) >> 3))
__device__ __forceinline__ int drev(int i) {
    return ((i & 7) << 6) | (i & 56) | (i >> 6);
}

// REGOUT=1: final stage leaves results in outreg[m] (position t+64m), no store/sync.
template<int INV, int REGOUT>
__device__ __forceinline__ void fft512_stages(float2 (*sd)[576], const float2* stw,
                                              float2* outreg) {
    int tid = threadIdx.x;
    float2* s = sd[tid >> 6];
    int t = tid & 63;
    {
        float2 a[8];
#pragma unroll
        for (int j = 0; j < 8; j++) { int p = 8*t + j; a[j] = s[FPAD(p)]; }
        dft8<INV>(a);
#pragma unroll
        for (int m = 0; m < 8; m++) { int p = 8*t + m; s[FPAD(p)] = a[m]; }
    }
    __syncthreads();
    {
        int k = t & 7, base = ((t >> 3) << 6) + k;
        float2 a[8];
        a[0] = s[FPAD(base)];
#pragma unroll
        for (int j = 1; j < 8; j++) {
            int p = base + 8*j;
            a[j] = ctw<INV>(s[FPAD(p)], stw[8*j*k]);
        }
        dft8<INV>(a);
#pragma unroll
        for (int m = 0; m < 8; m++) { int p = base + 8*m; s[FPAD(p)] = a[m]; }
    }
    __syncthreads();
    {
        float2 a[8];
        a[0] = s[FPAD(t)];
#pragma unroll
        for (int j = 1; j < 8; j++) {
            int p = t + 64*j;
            a[j] = ctw<INV>(s[FPAD(p)], stw[j*t]);
        }
        dft8<INV>(a);
        if (REGOUT) {
#pragma unroll
            for (int m = 0; m < 8; m++) outreg[m] = a[m];
        } else {
#pragma unroll
            for (int m = 0; m < 8; m++) { int p = t + 64*m; s[FPAD(p)] = a[m]; }
            __syncthreads();
        }
    }
}

// ---------------- forward FFT rows: z = noisy + i*clean (reg-direct out) -----
__global__ void __launch_bounds__(512)
fwd_rows_kernel(const float* __restrict__ noisy, const float* __restrict__ clean) {
    __shared__ float2 sd[8][576];
    __shared__ float2 stw[512];
    int tid = threadIdx.x;
    stw[tid] = g_tw[tid];
    int img = blockIdx.y;            // 0..23
    int r0  = blockIdx.x * 8;
    size_t base = (size_t)img * NPIX;
#pragma unroll
    for (int row = 0; row < 8; row++) {
        size_t gi = base + (size_t)(r0 + row) * 512 + tid;
        sd[row][FPAD(drev(tid))] = make_float2(noisy[gi], clean[gi]);
    }
    __syncthreads();
    float2 outr[8];
    fft512_stages<0, 1>(sd, stw, outr);
    int srow = tid >> 6, t = tid & 63;
    float2* dst = g_nfq + base + (size_t)(r0 + srow) * 512;
#pragma unroll
    for (int m = 0; m < 8; m++)
        dst[t + 64 * m] = outr[m];
}

// ---------------- forward FFT cols -------------------------------------------
__global__ void __launch_bounds__(512)
fwd_cols_kernel() {
    __shared__ float2 sd[8][576];
    __shared__ float2 stw[512];
    int tid = threadIdx.x;
    stw[tid] = g_tw[tid];
    int img = blockIdx.y;            // 0..23
    int c0  = blockIdx.x * 8;
    float2* buf = g_nfq + (size_t)img * NPIX;
    int c = tid & 7;
#pragma unroll
    for (int it = 0; it < 8; it++) {
        int r = it * 64 + (tid >> 3);
        sd[c][FPAD(drev(r))] = buf[(size_t)r * 512 + c0 + c];
    }
    __syncthreads();
    fft512_stages<0, 0>(sd, stw, nullptr);
#pragma unroll
    for (int it = 0; it < 8; it++) {
        int r = it * 64 + (tid >> 3);
        buf[(size_t)r * 512 + c0 + c] = sd[c][FPAD(r)];
    }
}

// ---------------- unpack Hermitian pair -> log-mag channels (f32) ------------
__global__ void unpack_logmag_kernel() {
    const int NC = 257;
    int idx = blockIdx.x * blockDim.x + threadIdx.x;
    if (idx >= NIMG * 512 * NC) return;
    int img = idx / (512 * NC);
    int rem = idx - img * (512 * NC);
    int r = rem / NC;
    int c = rem - r * NC;
    int mr = (512 - r) & 511, mc = (512 - c) & 511;
    float2 Zk = g_nfq[(size_t)img * NPIX + ((size_t)r << 9) + c];
    float2 Zm = g_nfq[(size_t)img * NPIX + ((size_t)mr << 9) + mc];
    float Nx = 0.5f * (Zk.x + Zm.x), Ny = 0.5f * (Zk.y - Zm.y);
    float Dx = 0.5f * (Zk.x - Zm.x), Dy = 0.5f * (Zk.y + Zm.y);
    float vN = __log10f(sqrtf(Nx * Nx + Ny * Ny) + 1.f);
    float vC = __log10f(sqrtf(Dx * Dx + Dy * Dy) + 1.f);
    int b = img / 3, ch = img - 3 * b;
    size_t o1 = ((size_t)((r + 256) & 511) << 9) + ((c + 256) & 511);
    size_t o2 = ((size_t)((mr + 256) & 511) << 9) + ((mc + 256) & 511);
    float* finN = g_fin + (size_t)(b * 6 + ch) * NPIX;
    float* finC = g_fin + (size_t)(b * 6 + 3 + ch) * NPIX;
    finN[o1] = vN; finN[o2] = vN;
    finC[o1] = vC; finC[o2] = vC;
}

// ---------------- bf16 MMA ---------------------------------------------------
#define MMA_BF16(d, a0,a1,a2,a3, b0,b1)                                        \
    asm("mma.sync.aligned.m16n8k16.row.col.f32.bf16.bf16.f32 "                 \
        "{%0,%1,%2,%3}, {%4,%5,%6,%7}, {%8,%9}, {%0,%1,%2,%3};"                \
        : "+f"(d[0]), "+f"(d[1]), "+f"(d[2]), "+f"(d[3])                       \
        : "r"(a0), "r"(a1), "r"(a2), "r"(a3), "r"(b0), "r"(b1))

// ---------------- implicit-GEMM 3x3 conv, bf16 m16n8k16 (round-14 proven) ----
template<int CIN, int COUT, int H, int W, bool POOL, bool GATHER, bool MEAN>
__global__ void __launch_bounds__(256)
convmma_kernel(const float* __restrict__ in,
               const float* __restrict__ noisy, const float* __restrict__ clean,
               const float* __restrict__ fin,
               const float* __restrict__ wgt,
               const float* __restrict__ bias, float* __restrict__ out) {
    constexpr int K   = CIN * 9;
    constexpr int KP  = (K + 15) & ~15;
    constexpr int NPAIR = KP / 2;
    constexpr int CS  = CIN + 2;              // bf16 elems per pixel slot
    constexpr int SIN_ELEMS = 18 * 36 * CS;   // bf16
    constexpr int OGC = COUT / 16;

    extern __shared__ char smemc[];
    __nv_bfloat16* sIn = (__nv_bfloat16*)smemc;
    unsigned* wPk = (unsigned*)(smemc + ((SIN_ELEMS * 2 + 15) & ~15));
    int* lutp = (int*)(wPk + NPAIR * 20);

    int tid = threadIdx.x;
    int bz = blockIdx.z;
    int og = bz % OGC;
    int b  = bz / OGC;
    int x0 = blockIdx.x * 32, y0 = blockIdx.y * 16;

    // ---- lut of byte offsets per k-pair
    for (int p = tid; p < NPAIR; p += 256) {
        int k = 2 * p, v = 0;
        if (k < K) {
            int tap = k / CIN, ic = k - tap * CIN;
            v = ((tap / 3) * 36 + (tap % 3)) * CS * 2 + ic * 2;
        }
        lutp[p] = v;
    }
    // ---- weights packed as bf16x2 fragments
    for (int e = tid; e < NPAIR * 16; e += 256) {
        int p = e >> 4, o = e & 15;
        int k = 2 * p;
        float w0 = 0.f, w1 = 0.f;
        if (k < K) {
            int tap = k / CIN, ic = k - tap * CIN;
            int base = ((og * 16 + o) * CIN + ic) * 9 + tap;
            w0 = wgt[base];
            w1 = wgt[base + 9];
        }
        __nv_bfloat162 pr = __floats2bfloat162_rn(w0, w1);
        wPk[p * 20 + o] = *(unsigned*)&pr;
    }
    // ---- input tile (halo): fused single loop (high MLP)
    for (int e = tid; e < 18 * 36 * CIN; e += 256) {
        int ic = e / 648;
        int rr = e - ic * 648;
        int r = rr / 36, cc = rr - r * 36;
        int gy = y0 + r - 1, gx = x0 + cc - 1;
        float v = 0.f;
        if (cc < 34 && (unsigned)gy < (unsigned)H && (unsigned)gx < (unsigned)W) {
            if (GATHER) {
                int grp = ic / 3, sub = ic - 3 * grp;
                const float* src =
                    (grp == 0) ? noisy + (size_t)(b * 3 + sub) * NPIX :
                    (grp == 1) ? fin   + (size_t)(b * 6 + sub) * NPIX :
                    (grp == 2) ? clean + (size_t)(b * 3 + sub) * NPIX :
                                 fin   + (size_t)(b * 6 + 3 + sub) * NPIX;
                v = src[((size_t)gy << 9) + gx];
            } else {
                v = in[((size_t)(b * CIN + ic) * H + gy) * W + gx];
            }
        }
        sIn[rr * CS + ic] = __float2bfloat16_rn(v);
    }
    __syncthreads();

    int lane = tid & 31, w = tid >> 5;
    int gid = lane >> 2, tig = lane & 3;

    float acc[4][2][4];
#pragma unroll
    for (int mt = 0; mt < 4; mt++)
#pragma unroll
        for (int nt = 0; nt < 2; nt++)
#pragma unroll
            for (int c = 0; c < 4; c++) acc[mt][nt][c] = 0.f;

    int Abase[4];
#pragma unroll
    for (int mt = 0; mt < 4; mt++)
        Abase[mt] = (((2 * w + (mt & 1)) * 36 + (mt >> 1) * 16 + gid) * CS) * 2;

    const char* sInB = (const char*)sIn;

#pragma unroll 3
    for (int kc = 0; kc < KP / 16; kc++) {
        int pb = kc * 8;
        int lp0 = lutp[pb + tig];
        int lp1 = lutp[pb + tig + 4];
        unsigned b0[2], b1[2];
#pragma unroll
        for (int nt = 0; nt < 2; nt++) {
            b0[nt] = wPk[(pb + tig) * 20 + nt * 8 + gid];
            b1[nt] = wPk[(pb + tig + 4) * 20 + nt * 8 + gid];
        }
#pragma unroll
        for (int mt = 0; mt < 4; mt++) {
            const char* pA = sInB + Abase[mt];
            unsigned a0 = *(const unsigned*)(pA + lp0);
            unsigned a1 = *(const unsigned*)(pA + lp0 + 8 * CS * 2);
            unsigned a2 = *(const unsigned*)(pA + lp1);
            unsigned a3 = *(const unsigned*)(pA + lp1 + 8 * CS * 2);
#pragma unroll
            for (int nt = 0; nt < 2; nt++)
                MMA_BF16(acc[mt][nt], a0, a1, a2, a3, b0[nt], b1[nt]);
        }
    }

    if (MEAN) {
        __shared__ float sred[8][16];
        int sblk = blockIdx.y * gridDim.x + blockIdx.x;   // 0..31
#pragma unroll
        for (int nt = 0; nt < 2; nt++)
#pragma unroll
            for (int j = 0; j < 2; j++) {
                int o = og * 16 + nt * 8 + 2 * tig + j;
                float bv = bias[o];
                float s = 0.f;
#pragma unroll
                for (int mt = 0; mt < 4; mt++)
                    s += fmaxf(acc[mt][nt][j] + bv, 0.f) +
                         fmaxf(acc[mt][nt][j + 2] + bv, 0.f);
                s += __shfl_xor_sync(0xffffffffu, s, 4);
                s += __shfl_xor_sync(0xffffffffu, s, 8);
                s += __shfl_xor_sync(0xffffffffu, s, 16);
                if (gid == 0) sred[w][nt * 8 + 2 * tig + j] = s;
            }
        __syncthreads();
        if (tid < 16) {
            float s = 0.f;
#pragma unroll
            for (int ww = 0; ww < 8; ww++) s += sred[ww][tid];
            out[(size_t)(b * COUT + og * 16 + tid) * 32 + sblk] = s;
        }
    } else if (POOL) {
        const int Ho = H / 2, Wo = W / 2;
        int oy = (y0 >> 1) + w;
#pragma unroll
        for (int half = 0; half < 2; half++) {
#pragma unroll
            for (int nt = 0; nt < 2; nt++)
#pragma unroll
                for (int c = 0; c < 2; c++) {
                    int o = og * 16 + nt * 8 + 2 * tig + c;
                    float bv = bias[o];
                    float sa = fmaxf(acc[half*2][nt][c]   + bv, 0.f) +
                               fmaxf(acc[half*2+1][nt][c] + bv, 0.f);
                    float sb = fmaxf(acc[half*2][nt][c+2]   + bv, 0.f) +
                               fmaxf(acc[half*2+1][nt][c+2] + bv, 0.f);
                    sa += __shfl_xor_sync(0xffffffffu, sa, 4);
                    sb += __shfl_xor_sync(0xffffffffu, sb, 4);
                    if (!(gid & 1)) {
                        int oxa = (x0 + half * 16 + gid) >> 1;
                        size_t base = ((size_t)(b * COUT + o) * Ho + oy) * Wo;
                        out[base + oxa]     = 0.25f * sa;
                        out[base + oxa + 4] = 0.25f * sb;
                    }
                }
        }
    }
}

// ---------------- fc1 (fused final mean reduction) ---------------------------
__global__ void __launch_bounds__(256)
fc1_kernel(const float* __restrict__ w, const float* __restrict__ bias,
           const float* __restrict__ part) {
    __shared__ float sf[64];
    int b = blockIdx.x, t = threadIdx.x;
    if (t < 64) {
        float s = 0.f;
        const float* p = part + (size_t)(b * 64 + t) * 32;
#pragma unroll
        for (int i = 0; i < 32; i++) s += p[i];
        sf[t] = s * (1.f / 16384.f);
    }
    __syncthreads();
    float s = 0.f;
    const float* wr = w + (size_t)t * 64;
#pragma unroll
    for (int i = 0; i < 64; i++) s = fmaf(wr[i], sf[i], s);
    g_h[b * 256 + t] = s + bias[t];
}

// ---------------- head -------------------------------------------------------
__global__ void __launch_bounds__(128)
head_kernel(const float* __restrict__ w, const float* __restrict__ bias) {
    __shared__ float sh[256];
    __shared__ float red[128];
    int j = blockIdx.x;
    int b = blockIdx.y;
    int t = threadIdx.x;
    for (int i = t; i < 256; i += 128) sh[i] = g_h[b * 256 + i];
    __syncthreads();
    float z = -3.4e38f;
    if (t < 100) {
        const float* wr = w + (size_t)(j * 100 + t) * 256;
        float s = 0.f;
        for (int i = 0; i < 256; i++) s = fmaf(wr[i], sh[i], s);
        z = (s + bias[j * 100 + t]) * 0.1f;
    }
    red[t] = z;
    __syncthreads();
    for (int off = 64; off; off >>= 1) {
        if (t < off) red[t] = fmaxf(red[t], red[t + off]);
        __syncthreads();
    }
    float m = red[0];
    __syncthreads();
    float p = (t < 100) ? __expf(z - m) : 0.f;
    red[t] = p;
    __syncthreads();
    for (int off = 64; off; off >>= 1) {
        if (t < off) red[t] += red[t + off];
        __syncthreads();
    }
    float S = red[0];
    __syncthreads();
    float rf = ((float)t + 1.0f) * 0.01f;
    red[t] = p * rf;
    __syncthreads();
    for (int off = 64; off; off >>= 1) {
        if (t < off) red[t] += red[t + off];
        __syncthreads();
    }
    if (t == 0) g_vset[b * 100 + j] = red[0] / S;
}

// ---------------- radial mask ------------------------------------------------
__global__ void mask_kernel(float* __restrict__ outMask) {
    int idx = blockIdx.x * blockDim.x + threadIdx.x;
    if (idx >= 8 * NPIX) return;
    int b = idx >> 18;
    int pix = idx & (NPIX - 1);
    int y = pix >> 9, x = pix & 511;
    float dy = (float)y - 256.f, dx = (float)x - 256.f;
    float dist = sqrtf(dy * dy + dx * dx);
    const float MAXR = 362.03867196751236f;
    int lo = 0, hi = 100;
    while (lo < hi) {
        int mid = (lo + hi) >> 1;
        float r = MAXR * (((float)(mid + 1)) * 0.01f);
        if (r <= dist) lo = mid + 1; else hi = mid;
    }
    outMask[idx] = (lo < 100) ? g_vset[b * 100 + lo] : 0.f;
}

// ---------------- inverse FFT rows: build D_a + i*D_b (reg-direct out) -------
__global__ void __launch_bounds__(512)
inv_rows_kernel(const float* __restrict__ maskp) {
    __shared__ float2 sd[8][576];
    __shared__ float2 stw[512];
    int tid = threadIdx.x;
    stw[tid] = g_tw[tid];
    int p   = blockIdx.y;     // 0..11
    int r0  = blockIdx.x * 8;
    int ia = 2 * p, ib = 2 * p + 1;
    int ba = ia / 3, bb = ib / 3;
    int c  = tid;
    int mc = (512 - c) & 511;
    int xs = (c + 256) & 511;
#pragma unroll
    for (int row = 0; row < 8; row++) {
        int gr = r0 + row;
        int mr = (512 - gr) & 511;
        int ys = (gr + 256) & 511;
        size_t ofk = ((size_t)gr << 9) + c;
        size_t ofm = ((size_t)mr << 9) + mc;
        float2 Zk = g_nfq[(size_t)ia * NPIX + ofk];
        float2 Zm = g_nfq[(size_t)ia * NPIX + ofm];
        float Nx = 0.5f*(Zk.x + Zm.x), Ny = 0.5f*(Zk.y - Zm.y);
        float Dx = 0.5f*(Zk.x - Zm.x), Dy = 0.5f*(Zk.y + Zm.y);
        float ma = maskp[(size_t)ba * NPIX + ((size_t)ys << 9) + xs];
        float Dax = ma * (Nx - Dy);
        float Day = ma * (Ny + Dx);
        Zk = g_nfq[(size_t)ib * NPIX + ofk];
        Zm = g_nfq[(size_t)ib * NPIX + ofm];
        Nx = 0.5f*(Zk.x + Zm.x); Ny = 0.5f*(Zk.y - Zm.y);
        Dx = 0.5f*(Zk.x - Zm.x); Dy = 0.5f*(Zk.y + Zm.y);
        float mb = maskp[(size_t)bb * NPIX + ((size_t)ys << 9) + xs];
        float Dbx = mb * (Nx - Dy);
        float Dby = mb * (Ny + Dx);
        sd[row][FPAD(drev(tid))] = make_float2(Dax - Dby, Day + Dbx);
    }
    __syncthreads();
    float2 outr[8];
    fft512_stages<1, 1>(sd, stw, outr);
    int srow = tid >> 6, t = tid & 63;
    float2* dst = g_cfq + (size_t)p * NPIX + (size_t)(r0 + srow) * 512;
#pragma unroll
    for (int m = 0; m < 8; m++)
        dst[t + 64 * m] = outr[m];
}

// ---------------- inverse FFT cols + hard/easy for both pair images ----------
__global__ void __launch_bounds__(512)
inv_cols_kernel(const float* __restrict__ clean, const float* __restrict__ noisy,
                float* __restrict__ hard, float* __restrict__ easy) {
    __shared__ float2 sd[8][576];
    __shared__ float2 stw[512];
    int tid = threadIdx.x;
    stw[tid] = g_tw[tid];
    int p   = blockIdx.y;     // 0..11
    int c0  = blockIdx.x * 8;
    float2* buf = g_cfq + (size_t)p * NPIX;
    int c = tid & 7;
#pragma unroll
    for (int it = 0; it < 8; it++) {
        int r = it * 64 + (tid >> 3);
        sd[c][FPAD(drev(r))] = buf[(size_t)r * 512 + c0 + c];
    }
    __syncthreads();
    fft512_stages<1, 0>(sd, stw, nullptr);
    const float scale = 1.f / 262144.f;
    int ia = 2 * p, ib = 2 * p + 1;
#pragma unroll
    for (int it = 0; it < 8; it++) {
        int r = it * 64 + (tid >> 3);
        float2 v = sd[c][FPAD(r)];
        float da = v.x * scale;
        float db = v.y * scale;
        size_t gia = (size_t)ia * NPIX + (size_t)r * 512 + c0 + c;
        size_t gib = (size_t)ib * NPIX + (size_t)r * 512 + c0 + c;
        hard[gia] = clean[gia] + da;
        easy[gia] = noisy[gia] - da;
        hard[gib] = clean[gib] + db;
        easy[gib] = noisy[gib] - db;
    }
}

// ---------------- launch ------------------------------------------------------
extern "C" void kernel_launch(void* const* d_in, const int* in_sizes, int n_in,
                              void* d_out, int out_size) {
    const float* clean = (const float*)d_in[0];
    const float* noisy = (const float*)d_in[1];
    const float* c1w = (const float*)d_in[2];
    const float* c1b = (const float*)d_in[3];
    const float* c2w = (const float*)d_in[4];
    const float* c2b = (const float*)d_in[5];
    const float* c3w = (const float*)d_in[6];
    const float* c3b = (const float*)d_in[7];
    const float* f1w = (const float*)d_in[8];
    const float* f1b = (const float*)d_in[9];
    const float* f2w = (const float*)d_in[10];
    const float* f2b = (const float*)d_in[11];

    float* hard  = (float*)d_out;
    float* easy  = hard + 6291456;
    float* maskp = easy + 6291456;

    float *p_fin, *p_p1, *p_p2, *p_part;
    cudaGetSymbolAddress((void**)&p_fin, g_fin);
    cudaGetSymbolAddress((void**)&p_p1, g_p1);
    cudaGetSymbolAddress((void**)&p_p2, g_p2);
    cudaGetSymbolAddress((void**)&p_part, g_part);

    // smem bytes: align(sIn) + wPk(NPAIR*20*4) + lutp(NPAIR*4)
    const int smem1 = ((18*36*14*2 + 15) & ~15) + 56 * 20 * 4 + 56 * 4;
    const int smem2 = ((18*36*18*2 + 15) & ~15) + 72 * 20 * 4 + 72 * 4;
    const int smem3 = ((18*36*34*2 + 15) & ~15) + 144 * 20 * 4 + 144 * 4;
    cudaFuncSetAttribute(convmma_kernel<12, 16, 512, 512, true, true, false>,
                         cudaFuncAttributeMaxDynamicSharedMemorySize, smem1);
    cudaFuncSetAttribute(convmma_kernel<16, 32, 256, 256, true, false, false>,
                         cudaFuncAttributeMaxDynamicSharedMemorySize, smem2);
    cudaFuncSetAttribute(convmma_kernel<32, 64, 128, 128, false, false, true>,
                         cudaFuncAttributeMaxDynamicSharedMemorySize, smem3);

    init_tw_kernel<<<1, 512>>>();

    fwd_rows_kernel<<<dim3(64, 24), 512>>>(noisy, clean);
    fwd_cols_kernel<<<dim3(64, 24), 512>>>();
    unpack_logmag_kernel<<<(NIMG * 512 * 257 + 255) / 256, 256>>>();

    convmma_kernel<12, 16, 512, 512, true, true, false><<<dim3(16, 32, 8), 256, smem1>>>(
        nullptr, noisy, clean, p_fin, c1w, c1b, p_p1);
    convmma_kernel<16, 32, 256, 256, true, false, false><<<dim3(8, 16, 16), 256, smem2>>>(
        p_p1, nullptr, nullptr, nullptr, c2w, c2b, p_p2);
    convmma_kernel<32, 64, 128, 128, false, false, true><<<dim3(4, 8, 32), 256, smem3>>>(
        p_p2, nullptr, nullptr, nullptr, c3w, c3b, p_part);

    fc1_kernel<<<8, 256>>>(f1w, f1b, p_part);
    head_kernel<<<dim3(100, 8), 128>>>(f2w, f2b);

    mask_kernel<<<(8 * NPIX + 255) / 256, 256>>>(maskp);
    inv_rows_kernel<<<dim3(64, 12), 512>>>(maskp);
    inv_cols_kernel<<<dim3(64, 12), 512>>>(clean, noisy, hard, easy);
}